// round 15
// baseline (speedup 1.0000x reference)
#include <cuda_runtime.h>
#include <cuda_bf16.h>
#include <cstdint>

#define S_LEN 4096
#define HID   1024
#define NH    16
#define HD    64
#define WIN   512
#define HALF  256
#define QT    32
#define GK    1024
#define GN    1024

// ---- scratch (no cudaMalloc allowed); referenced only from device code ----
__device__ __nv_bfloat16 g_xh[S_LEN * HID];   // X split (later: ctx split)
__device__ __nv_bfloat16 g_xl[S_LEN * HID];
__device__ __nv_bfloat16 g_wth[4 * HID * HID];
__device__ __nv_bfloat16 g_wtl[4 * HID * HID];
__device__ __nv_bfloat16 g_qh[S_LEN * HID];
__device__ __nv_bfloat16 g_ql[S_LEN * HID];
__device__ __nv_bfloat16 g_kh[S_LEN * HID];
__device__ __nv_bfloat16 g_kl[S_LEN * HID];
__device__ __nv_bfloat16 g_vh[S_LEN * HID];
__device__ __nv_bfloat16 g_vl[S_LEN * HID];

__device__ __forceinline__ uint32_t smem_u32(const void* p) {
    uint32_t a;
    asm("{ .reg .u64 t; cvta.to.shared.u64 t, %1; cvt.u32.u64 %0, t; }"
        : "=r"(a) : "l"(p));
    return a;
}

#define CP16(dst, src) \
    asm volatile("cp.async.cg.shared.global [%0], [%1], 16;" \
                 :: "r"(dst), "l"(src) : "memory")
#define CP16Z(dst, src, sz) \
    asm volatile("cp.async.cg.shared.global [%0], [%1], 16, %2;" \
                 :: "r"(dst), "l"(src), "r"(sz) : "memory")
#define CP_COMMIT() asm volatile("cp.async.commit_group;" ::: "memory")
#define CP_WAIT1()  asm volatile("cp.async.wait_group 1;" ::: "memory")
#define CP_WAIT0()  asm volatile("cp.async.wait_group 0;" ::: "memory")

#define LDSM4(r, a) \
    asm volatile("ldmatrix.sync.aligned.m8n8.x4.shared.b16 {%0,%1,%2,%3}, [%4];" \
                 : "=r"((r)[0]), "=r"((r)[1]), "=r"((r)[2]), "=r"((r)[3]) \
                 : "r"(a))
#define LDSM4T(r, a) \
    asm volatile("ldmatrix.sync.aligned.m8n8.x4.trans.shared.b16 {%0,%1,%2,%3}, [%4];" \
                 : "=r"((r)[0]), "=r"((r)[1]), "=r"((r)[2]), "=r"((r)[3]) \
                 : "r"(a))

#define MMA16816(d, a, b0, b1) \
    asm volatile("mma.sync.aligned.m16n8k16.row.col.f32.bf16.bf16.f32 " \
                 "{%0,%1,%2,%3}, {%4,%5,%6,%7}, {%8,%9}, {%0,%1,%2,%3};" \
                 : "+f"((d)[0]), "+f"((d)[1]), "+f"((d)[2]), "+f"((d)[3]) \
                 : "r"((a)[0]), "r"((a)[1]), "r"((a)[2]), "r"((a)[3]), \
                   "r"(b0), "r"(b1))

__device__ __forceinline__ void split_bf16(float v, __nv_bfloat16& h,
                                           __nv_bfloat16& l) {
    h = __float2bfloat16(v);
    l = __float2bfloat16(v - __bfloat162float(h));
}
__device__ __forceinline__ uint32_t pk2(__nv_bfloat16 a, __nv_bfloat16 b) {
    return ((uint32_t)__bfloat16_as_ushort(b) << 16) | __bfloat16_as_ushort(a);
}
__device__ __forceinline__ void sp2(float a, float b, uint32_t& hp, uint32_t& lp) {
    __nv_bfloat16 ha, la, hb, lb;
    split_bf16(a, ha, la);
    split_bf16(b, hb, lb);
    hp = pk2(ha, hb);
    lp = pk2(la, lb);
}

// ============================================================================
// convert X -> g_xh/g_xl
// ============================================================================
__global__ __launch_bounds__(256)
void conv_act(const float* __restrict__ src)
{
    size_t i = (size_t)blockIdx.x * 256 + threadIdx.x;
    float4 v = *(const float4*)(src + i * 4);
    uint2 hp, lp;
    sp2(v.x, v.y, hp.x, lp.x);
    sp2(v.z, v.w, hp.y, lp.y);
    *(uint2*)&g_xh[i * 4] = hp;
    *(uint2*)&g_xl[i * 4] = lp;
}

// ============================================================================
// convert + transpose weight W[K,N] -> g_wth/g_wtl[N,K] at offset woff
// ============================================================================
__global__ __launch_bounds__(256)
void conv_w_t(const float* __restrict__ W, int woff)
{
    __shared__ float tile[32][33];
    const int tx = threadIdx.x, ty = threadIdx.y;
#pragma unroll
    for (int j = 0; j < 4; j++)
        tile[ty + 8 * j][tx] =
            W[(size_t)(blockIdx.y * 32 + ty + 8 * j) * HID + blockIdx.x * 32 + tx];
    __syncthreads();
#pragma unroll
    for (int j = 0; j < 4; j++) {
        float v = tile[tx][ty + 8 * j];
        __nv_bfloat16 h, l;
        split_bf16(v, h, l);
        size_t o = (size_t)woff +
                   (size_t)(blockIdx.x * 32 + ty + 8 * j) * HID + blockIdx.y * 32 + tx;
        g_wth[o] = h;
        g_wtl[o] = l;
    }
}

// ============================================================================
// Big-tile HMMA split-bf16 GEMM body (unchanged from 710.6us version)
// ============================================================================
#define AST   40
#define GBUFB 61440
#define GSMEM (2 * GBUFB)

__device__ __forceinline__ void hgemm_body(
    int woff, const float* __restrict__ bias,
    float* __restrict__ Cf,
    __nv_bfloat16* __restrict__ Ch, __nv_bfloat16* __restrict__ Cl,
    int m0, int n0)
{
    extern __shared__ __align__(128) char hsm[];
    const int t = threadIdx.x, wid = t >> 5, lane = t & 31;
    const uint32_t sb = smem_u32(hsm);

    const int lrow = t >> 1;
    const int segH = (t & 1) * 16;
    const __nv_bfloat16* gsrc[6];
    uint32_t sdst[6];
    gsrc[0] = g_xh + (size_t)(m0 + lrow) * GK + segH;
    sdst[0] = (uint32_t)(lrow * 80) + segH * 2;
    gsrc[1] = g_xh + (size_t)(m0 + 128 + lrow) * GK + segH;
    sdst[1] = (uint32_t)((128 + lrow) * 80) + segH * 2;
    gsrc[2] = g_xl + (size_t)(m0 + lrow) * GK + segH;
    sdst[2] = 20480u + (uint32_t)(lrow * 80) + segH * 2;
    gsrc[3] = g_xl + (size_t)(m0 + 128 + lrow) * GK + segH;
    sdst[3] = 20480u + (uint32_t)((128 + lrow) * 80) + segH * 2;
    gsrc[4] = g_wth + woff + (size_t)(n0 + lrow) * GK + segH;
    sdst[4] = 40960u + (uint32_t)(lrow * 80) + segH * 2;
    gsrc[5] = g_wtl + woff + (size_t)(n0 + lrow) * GK + segH;
    sdst[5] = 51200u + (uint32_t)(lrow * 80) + segH * 2;

    const int warp_m = wid & 3, warp_n = wid >> 2;
    const int l16 = lane & 15, lh8 = (lane >> 4) * 8;

    float acc[4][8][4];
#pragma unroll
    for (int i = 0; i < 4; i++)
#pragma unroll
        for (int j = 0; j < 8; j++)
#pragma unroll
            for (int e = 0; e < 4; e++) acc[i][j][e] = 0.f;

#define GISSUE(c) do {                                                       \
    const uint32_t bo_ = sb + ((c) & 1) * GBUFB;                             \
    const int ko_ = (c) * 32;                                                \
    _Pragma("unroll")                                                        \
    for (int r_ = 0; r_ < 6; r_++) {                                         \
        CP16(bo_ + sdst[r_],      gsrc[r_] + ko_);                           \
        CP16(bo_ + sdst[r_] + 16, gsrc[r_] + ko_ + 8);                       \
    }                                                                        \
    CP_COMMIT();                                                             \
} while (0)

    GISSUE(0);
    for (int c = 0; c < 32; c++) {
        if (c + 1 < 32) { GISSUE(c + 1); CP_WAIT1(); }
        else            { CP_WAIT0(); }
        __syncthreads();

        const uint32_t ab = sb + (c & 1) * GBUFB;
#pragma unroll
        for (int ks = 0; ks < 32; ks += 16) {
            uint32_t ah[4][4], al[4][4];
#pragma unroll
            for (int mf = 0; mf < 4; mf++) {
                uint32_t ad = ab +
                    (uint32_t)((warp_m * 64 + mf * 16 + l16) * AST + ks + lh8) * 2;
                LDSM4(ah[mf], ad);
                LDSM4(al[mf], ad + 20480);
            }
#pragma unroll
            for (int nf = 0; nf < 4; nf++) {
                uint32_t bh[4], bl[4];
                uint32_t bd = ab + 40960u +
                    (uint32_t)((warp_n * 64 + nf * 16 + l16) * AST + ks + lh8) * 2;
                LDSM4(bh, bd);
                LDSM4(bl, bd + 10240);
#pragma unroll
                for (int mf = 0; mf < 4; mf++)
#pragma unroll
                    for (int j = 0; j < 2; j++) {
                        float* d = acc[mf][nf * 2 + j];
                        MMA16816(d, ah[mf], bh[j], bh[j + 2]);
                        MMA16816(d, ah[mf], bl[j], bl[j + 2]);
                        MMA16816(d, al[mf], bh[j], bh[j + 2]);
                    }
            }
        }
        __syncthreads();
    }

    const int er = lane >> 2, ec = (lane & 3) * 2;
#pragma unroll
    for (int mf = 0; mf < 4; mf++)
#pragma unroll
        for (int n8 = 0; n8 < 8; n8++) {
            int m = m0 + warp_m * 64 + mf * 16 + er;
            int n = n0 + warp_n * 64 + n8 * 8 + ec;
            float bx = bias[n], by = bias[n + 1];
            float* a4 = acc[mf][n8];
            if (Cf) {
                *(float2*)&Cf[(size_t)m * GN + n] =
                    make_float2(a4[0] + bx, a4[1] + by);
                *(float2*)&Cf[(size_t)(m + 8) * GN + n] =
                    make_float2(a4[2] + bx, a4[3] + by);
            } else {
                uint32_t hp, lp;
                sp2(a4[0] + bx, a4[1] + by, hp, lp);
                *(uint32_t*)&Ch[(size_t)m * GN + n] = hp;
                *(uint32_t*)&Cl[(size_t)m * GN + n] = lp;
                sp2(a4[2] + bx, a4[3] + by, hp, lp);
                *(uint32_t*)&Ch[(size_t)(m + 8) * GN + n] = hp;
                *(uint32_t*)&Cl[(size_t)(m + 8) * GN + n] = lp;
            }
        }
#undef GISSUE
}

__global__ __launch_bounds__(256, 1)
void hgemm_qkv(const float* __restrict__ bq, const float* __restrict__ bk,
               const float* __restrict__ bv)
{
    const int which = blockIdx.x >> 3;
    const int n0 = (blockIdx.x & 7) * 128;
    const int m0 = blockIdx.y * 256;
    __nv_bfloat16 *Ch, *Cl;
    const float* bias;
    if (which == 0)      { Ch = g_qh; Cl = g_ql; bias = bq; }
    else if (which == 1) { Ch = g_kh; Cl = g_kl; bias = bk; }
    else                 { Ch = g_vh; Cl = g_vl; bias = bv; }
    hgemm_body(which * HID * HID, bias, nullptr, Ch, Cl, m0, n0);
}

__global__ __launch_bounds__(256, 1)
void hgemm_o(const float* __restrict__ bo, float* __restrict__ out)
{
    hgemm_body(3 * HID * HID, bo, out, nullptr, nullptr,
               blockIdx.y * 256, blockIdx.x * 128);
}

// ============================================================================
// Fused HMMA sliding-window attention (FA2-style register P reuse).
// One chunk loop: stage K+V (cp.async, pre-split), QK MMAs -> exp in regs ->
// A-fragments for PV MMAs with V B-frags via ldmatrix.trans. P smem kept only
// for the probs output. Cross-warp ctx reduction at the end.
// smem (bytes):
//   Ph 0 (35328) | Pl 35328 (35328)
//   Kh 70656 (9216) | Kl 79872 (9216) | Vh 89088 (9216) | Vl 98304 (9216)
//   Q hi/lo overlays Kh/Kl area before the loop; red (8x16x64 f32 = 32768)
//   overlays K/V after the loop. part @107520 (1024) | sinv @108544 (128)
// ============================================================================
#define KSTH  72
#define PSTH  552
#define APHB  0
#define APLB  35328
#define AKHB  70656
#define AKLB  79872
#define AVHB  89088
#define AVLB  98304
#define AQHB  70656
#define AQLB  75264
#define ARED  70656
#define APRT  107520
#define ASNV  108544
#define ASMEM 108672

__global__ __launch_bounds__(256, 2)
void attn_kernel(float* __restrict__ probs, int write_probs)
{
    extern __shared__ __align__(128) char am[];
    const uint32_t sb = smem_u32(am);

    const int t    = threadIdx.x;
    const int lane = t & 31;
    const int w    = t >> 5;
    const int q0   = blockIdx.x * QT;
    const int h    = blockIdx.y;
    const int hoff = h * HD;
    const int kmin = q0 - HALF;

    float* part = (float*)(am + APRT);
    float* sinv = (float*)(am + ASNV);
    part[t] = 0.f;

    // ---- stage Q (pre-split) via cp.async into the K-buffer overlay ----
    if (t < 128) {
        int row = t >> 2, dg = (t & 3) * 16;
        const __nv_bfloat16* sh = g_qh + (size_t)(q0 + row) * HID + hoff + dg;
        const __nv_bfloat16* sl = g_ql + (size_t)(q0 + row) * HID + hoff + dg;
        uint32_t o = sb + (uint32_t)(row * KSTH + dg) * 2;
        CP16(o + AQHB, sh);
        CP16(o + AQHB + 16, sh + 8);
        CP16(o + AQLB, sl);
        CP16(o + AQLB + 16, sl + 8);
    }
    CP_COMMIT();
    CP_WAIT0();
    __syncthreads();

    const int mt  = w & 1;
    const int nb  = (w >> 1) * 16;
    const int l16 = lane & 15, lh8 = (lane >> 4) * 8;

    uint32_t qh[4][4], ql[4][4];
#pragma unroll
    for (int ks = 0; ks < 4; ks++) {
        uint32_t ad = sb + AQHB + (uint32_t)((mt * 16 + l16) * KSTH + ks * 16 + lh8) * 2;
        LDSM4(qh[ks], ad);
        LDSM4(ql[ks], ad + (AQLB - AQHB));
    }
    __syncthreads();   // Q frags read before K staging overwrites overlay

    float rs0 = 0.f, rs1 = 0.f;
    const int r0 = mt * 16 + (lane >> 2), r1 = r0 + 8;

    float acc2[8][4];
#pragma unroll
    for (int j = 0; j < 8; j++)
#pragma unroll
        for (int e = 0; e < 4; e++) acc2[j][e] = 0.f;

    for (int cc = 0; cc < 9; cc++) {
        const int cb = cc * 64;
        const int W  = (cc == 8) ? 32 : 64;

        // stage K + V (pre-split) via cp.async; zero-fill OOB keys
        {
            int row = t >> 2, dg = (t & 3) * 16;
            if (row < W) {
                int key = kmin + cb + row;
                bool ok = (key >= 0 && key < S_LEN);
                int keyc = ok ? key : 0;
                int sz = ok ? 16 : 0;
                size_t go = (size_t)keyc * HID + hoff + dg;
                uint32_t o = sb + (uint32_t)(row * KSTH + dg) * 2;
                CP16Z(o + AKHB, g_kh + go, sz);
                CP16Z(o + AKHB + 16, g_kh + go + 8, sz);
                CP16Z(o + AKLB, g_kl + go, sz);
                CP16Z(o + AKLB + 16, g_kl + go + 8, sz);
                CP16Z(o + AVHB, g_vh + go, sz);
                CP16Z(o + AVHB + 16, g_vh + go + 8, sz);
                CP16Z(o + AVLB, g_vl + go, sz);
                CP16Z(o + AVLB + 16, g_vl + go + 8, sz);
            }
        }
        CP_COMMIT();
        CP_WAIT0();
        __syncthreads();

        if (nb < W) {
            // ---- QK: 16q x 16key tile ----
            float acc[2][4];
#pragma unroll
            for (int j = 0; j < 2; j++)
#pragma unroll
                for (int e = 0; e < 4; e++) acc[j][e] = 0.f;

#pragma unroll
            for (int ks = 0; ks < 4; ks++) {
                uint32_t bh[4], bl[4];
                uint32_t bd = sb + AKHB +
                    (uint32_t)((nb + l16) * KSTH + ks * 16 + lh8) * 2;
                LDSM4(bh, bd);
                LDSM4(bl, bd + (AKLB - AKHB));
#pragma unroll
                for (int j = 0; j < 2; j++) {
                    MMA16816(acc[j], qh[ks], bh[j], bh[j + 2]);
                    MMA16816(acc[j], qh[ks], bl[j], bl[j + 2]);
                    MMA16816(acc[j], ql[ks], bh[j], bh[j + 2]);
                }
            }

            // ---- exp + mask -> P fragments (registers) + P smem (probs) ----
            uint32_t aPh[4], aPl[4];
#pragma unroll
            for (int j = 0; j < 2; j++) {
                int c0 = cb + nb + j * 8 + (lane & 3) * 2;
                float o00 = ((unsigned)(c0 - r0) < WIN)
                            ? __expf(acc[j][0] * 0.125f) : 0.f;
                float o01 = ((unsigned)(c0 + 1 - r0) < WIN)
                            ? __expf(acc[j][1] * 0.125f) : 0.f;
                float o10 = ((unsigned)(c0 - r1) < WIN)
                            ? __expf(acc[j][2] * 0.125f) : 0.f;
                float o11 = ((unsigned)(c0 + 1 - r1) < WIN)
                            ? __expf(acc[j][3] * 0.125f) : 0.f;
                rs0 += o00 + o01;
                rs1 += o10 + o11;
                uint32_t hp0, lp0, hp1, lp1;
                sp2(o00, o01, hp0, lp0);
                sp2(o10, o11, hp1, lp1);
                aPh[j * 2]     = hp0;
                aPl[j * 2]     = lp0;
                aPh[j * 2 + 1] = hp1;
                aPl[j * 2 + 1] = lp1;
                *(uint32_t*)(am + APHB + (uint32_t)(r0 * PSTH + c0) * 2) = hp0;
                *(uint32_t*)(am + APLB + (uint32_t)(r0 * PSTH + c0) * 2) = lp0;
                *(uint32_t*)(am + APHB + (uint32_t)(r1 * PSTH + c0) * 2) = hp1;
                *(uint32_t*)(am + APLB + (uint32_t)(r1 * PSTH + c0) * 2) = lp1;
            }

            // ---- PV: P(16q x 16key) @ V(16key x 64d), V B-frags via trans ----
#pragma unroll
            for (int nf = 0; nf < 4; nf++) {
                uint32_t vh4[4], vl4[4];
                uint32_t vd = sb + AVHB +
                    (uint32_t)((nb + l16) * KSTH + nf * 16 + lh8) * 2;
                LDSM4T(vh4, vd);
                LDSM4T(vl4, vd + (AVLB - AVHB));
#pragma unroll
                for (int j2 = 0; j2 < 2; j2++) {
                    float* d = acc2[nf * 2 + j2];
                    MMA16816(d, aPh, vh4[j2 * 2], vh4[j2 * 2 + 1]);
                    MMA16816(d, aPh, vl4[j2 * 2], vl4[j2 * 2 + 1]);
                    MMA16816(d, aPl, vh4[j2 * 2], vh4[j2 * 2 + 1]);
                }
            }
        }
        __syncthreads();   // compute done before next chunk staging
    }

    // ---- deterministic row sums ----
    rs0 += __shfl_xor_sync(0xFFFFFFFFu, rs0, 1);
    rs0 += __shfl_xor_sync(0xFFFFFFFFu, rs0, 2);
    rs1 += __shfl_xor_sync(0xFFFFFFFFu, rs1, 1);
    rs1 += __shfl_xor_sync(0xFFFFFFFFu, rs1, 2);
    if ((lane & 3) == 0) {
        part[w * 32 + r0] = rs0;
        part[w * 32 + r1] = rs1;
    }
    __syncthreads();
    if (t < 32) {
        float s = 0.f;
#pragma unroll
        for (int w8 = 0; w8 < 8; w8++) s += part[w8 * 32 + t];
        sinv[t] = 1.f / s;
    }
    __syncthreads();

    // ---- probs write ----
    if (write_probs) {
        float* pr = probs + ((size_t)h * S_LEN + q0) * WIN;
        for (int idx = t; idx < QT * WIN; idx += 256) {
            int qi = idx >> 9, ww = idx & (WIN - 1);
            uint32_t o = (uint32_t)(qi * PSTH + qi + ww) * 2;
            float ph = __bfloat162float(*(__nv_bfloat16*)(am + APHB + o));
            float pl = __bfloat162float(*(__nv_bfloat16*)(am + APLB + o));
            pr[(size_t)qi * WIN + ww] = (ph + pl) * sinv[qi];
        }
    }

    // ---- cross-warp ctx reduction (red overlays K/V area) ----
    {
        char* red = am + ARED + w * 4096;
        const int g = lane >> 2, dc = (lane & 3) * 2;
#pragma unroll
        for (int n8 = 0; n8 < 8; n8++) {
            int d = n8 * 8 + dc;
            *(float2*)(red + g * 256 + d * 4) =
                make_float2(acc2[n8][0], acc2[n8][1]);
            *(float2*)(red + (g + 8) * 256 + d * 4) =
                make_float2(acc2[n8][2], acc2[n8][3]);
        }
    }
    __syncthreads();

    // ---- sum 4 key-slice partials per q-tile, scale, split-write ----
    {
        int q = t >> 3, d0 = (t & 7) * 8;
        int mtq = q >> 4, qr = q & 15;
        float v[8];
#pragma unroll
        for (int e = 0; e < 8; e++) v[e] = 0.f;
#pragma unroll
        for (int wb = 0; wb < 4; wb++) {
            const float* rb =
                (const float*)(am + ARED + (mtq + wb * 2) * 4096 + qr * 256 + d0 * 4);
#pragma unroll
            for (int e = 0; e < 8; e++) v[e] += rb[e];
        }
        float iv = sinv[q];
        size_t o = (size_t)(q0 + q) * HID + hoff + d0;
#pragma unroll
        for (int p = 0; p < 4; p++) {
            uint32_t hp, lp;
            sp2(v[p * 2] * iv, v[p * 2 + 1] * iv, hp, lp);
            *(uint32_t*)&g_xh[o + p * 2] = hp;
            *(uint32_t*)&g_xl[o + p * 2] = lp;
        }
    }
}

// ============================================================================
extern "C" void kernel_launch(void* const* d_in, const int* in_sizes, int n_in,
                              void* d_out, int out_size)
{
    const float* X  = (const float*)d_in[0];
    const float* Wq = (const float*)d_in[1];
    const float* bq = (const float*)d_in[2];
    const float* Wk = (const float*)d_in[3];
    const float* bk = (const float*)d_in[4];
    const float* Wv = (const float*)d_in[5];
    const float* bv = (const float*)d_in[6];
    const float* Wo = (const float*)d_in[7];
    const float* bo = (const float*)d_in[8];

    float* out = (float*)d_out;
    const size_t OUT_ELEMS   = (size_t)S_LEN * HID;
    const size_t PROBS_ELEMS = (size_t)NH * S_LEN * WIN;
    float* probs = out + OUT_ELEMS;
    int write_probs = ((size_t)out_size >= OUT_ELEMS + PROBS_ELEMS) ? 1 : 0;

    cudaFuncSetAttribute(attn_kernel,
                         cudaFuncAttributeMaxDynamicSharedMemorySize, ASMEM);
    cudaFuncSetAttribute(hgemm_qkv,
                         cudaFuncAttributeMaxDynamicSharedMemorySize, GSMEM);
    cudaFuncSetAttribute(hgemm_o,
                         cudaFuncAttributeMaxDynamicSharedMemorySize, GSMEM);

    conv_act<<<(S_LEN * HID) / 1024, 256>>>(X);
    dim3 ct(32, 8), cg(HID / 32, HID / 32);
    conv_w_t<<<cg, ct>>>(Wq, 0);
    conv_w_t<<<cg, ct>>>(Wk, HID * HID);
    conv_w_t<<<cg, ct>>>(Wv, 2 * HID * HID);
    conv_w_t<<<cg, ct>>>(Wo, 3 * HID * HID);

    hgemm_qkv<<<dim3(24, 16), 256, GSMEM>>>(bq, bk, bv);

    dim3 agrid(S_LEN / QT, NH);
    attn_kernel<<<agrid, 256, ASMEM>>>(probs, write_probs);

    hgemm_o<<<dim3(8, 16), 256, GSMEM>>>(bo, out);
}

// round 16
// speedup vs baseline: 1.0000x; 1.0000x over previous
#include <cuda_runtime.h>
#include <cuda_bf16.h>
#include <cstdint>

#define S_LEN 4096
#define HID   1024
#define NH    16
#define HD    64
#define WIN   512
#define HALF  256
#define QT    32
#define GK    1024
#define GN    1024

// ---- scratch (no cudaMalloc allowed); referenced only from device code ----
__device__ __nv_bfloat16 g_xh[S_LEN * HID];   // X split (later: ctx split)
__device__ __nv_bfloat16 g_xl[S_LEN * HID];
__device__ __nv_bfloat16 g_wth[4 * HID * HID];
__device__ __nv_bfloat16 g_wtl[4 * HID * HID];
__device__ __nv_bfloat16 g_qh[S_LEN * HID];
__device__ __nv_bfloat16 g_ql[S_LEN * HID];
__device__ __nv_bfloat16 g_kh[S_LEN * HID];
__device__ __nv_bfloat16 g_kl[S_LEN * HID];
__device__ __nv_bfloat16 g_vh[S_LEN * HID];
__device__ __nv_bfloat16 g_vl[S_LEN * HID];

__device__ __forceinline__ uint32_t smem_u32(const void* p) {
    uint32_t a;
    asm("{ .reg .u64 t; cvta.to.shared.u64 t, %1; cvt.u32.u64 %0, t; }"
        : "=r"(a) : "l"(p));
    return a;
}

#define CP16(dst, src) \
    asm volatile("cp.async.cg.shared.global [%0], [%1], 16;" \
                 :: "r"(dst), "l"(src) : "memory")
#define CP16Z(dst, src, sz) \
    asm volatile("cp.async.cg.shared.global [%0], [%1], 16, %2;" \
                 :: "r"(dst), "l"(src), "r"(sz) : "memory")
#define CP_COMMIT() asm volatile("cp.async.commit_group;" ::: "memory")
#define CP_WAIT1()  asm volatile("cp.async.wait_group 1;" ::: "memory")
#define CP_WAIT0()  asm volatile("cp.async.wait_group 0;" ::: "memory")

#define LDSM4(r, a) \
    asm volatile("ldmatrix.sync.aligned.m8n8.x4.shared.b16 {%0,%1,%2,%3}, [%4];" \
                 : "=r"((r)[0]), "=r"((r)[1]), "=r"((r)[2]), "=r"((r)[3]) \
                 : "r"(a))
#define LDSM4T(r, a) \
    asm volatile("ldmatrix.sync.aligned.m8n8.x4.trans.shared.b16 {%0,%1,%2,%3}, [%4];" \
                 : "=r"((r)[0]), "=r"((r)[1]), "=r"((r)[2]), "=r"((r)[3]) \
                 : "r"(a))

#define MMA16816(d, a, b0, b1) \
    asm volatile("mma.sync.aligned.m16n8k16.row.col.f32.bf16.bf16.f32 " \
                 "{%0,%1,%2,%3}, {%4,%5,%6,%7}, {%8,%9}, {%0,%1,%2,%3};" \
                 : "+f"((d)[0]), "+f"((d)[1]), "+f"((d)[2]), "+f"((d)[3]) \
                 : "r"((a)[0]), "r"((a)[1]), "r"((a)[2]), "r"((a)[3]), \
                   "r"(b0), "r"(b1))

__device__ __forceinline__ void split_bf16(float v, __nv_bfloat16& h,
                                           __nv_bfloat16& l) {
    h = __float2bfloat16(v);
    l = __float2bfloat16(v - __bfloat162float(h));
}
__device__ __forceinline__ uint32_t pk2(__nv_bfloat16 a, __nv_bfloat16 b) {
    return ((uint32_t)__bfloat16_as_ushort(b) << 16) | __bfloat16_as_ushort(a);
}
__device__ __forceinline__ void sp2(float a, float b, uint32_t& hp, uint32_t& lp) {
    __nv_bfloat16 ha, la, hb, lb;
    split_bf16(a, ha, la);
    split_bf16(b, hb, lb);
    hp = pk2(ha, hb);
    lp = pk2(la, lb);
}

// ============================================================================
// convert X -> g_xh/g_xl
// ============================================================================
__global__ __launch_bounds__(256)
void conv_act(const float* __restrict__ src)
{
    size_t i = (size_t)blockIdx.x * 256 + threadIdx.x;
    float4 v = *(const float4*)(src + i * 4);
    uint2 hp, lp;
    sp2(v.x, v.y, hp.x, lp.x);
    sp2(v.z, v.w, hp.y, lp.y);
    *(uint2*)&g_xh[i * 4] = hp;
    *(uint2*)&g_xl[i * 4] = lp;
}

// ============================================================================
// convert + transpose weight W[K,N] -> g_wth/g_wtl[N,K] at offset woff
// ============================================================================
__global__ __launch_bounds__(256)
void conv_w_t(const float* __restrict__ W, int woff)
{
    __shared__ float tile[32][33];
    const int tx = threadIdx.x, ty = threadIdx.y;
#pragma unroll
    for (int j = 0; j < 4; j++)
        tile[ty + 8 * j][tx] =
            W[(size_t)(blockIdx.y * 32 + ty + 8 * j) * HID + blockIdx.x * 32 + tx];
    __syncthreads();
#pragma unroll
    for (int j = 0; j < 4; j++) {
        float v = tile[tx][ty + 8 * j];
        __nv_bfloat16 h, l;
        split_bf16(v, h, l);
        size_t o = (size_t)woff +
                   (size_t)(blockIdx.x * 32 + ty + 8 * j) * HID + blockIdx.y * 32 + tx;
        g_wth[o] = h;
        g_wtl[o] = l;
    }
}

// ============================================================================
// Big-tile HMMA split-bf16 GEMM body (unchanged from 710.6us version)
// ============================================================================
#define AST   40
#define GBUFB 61440
#define GSMEM (2 * GBUFB)

__device__ __forceinline__ void hgemm_body(
    int woff, const float* __restrict__ bias,
    float* __restrict__ Cf,
    __nv_bfloat16* __restrict__ Ch, __nv_bfloat16* __restrict__ Cl,
    int m0, int n0)
{
    extern __shared__ __align__(128) char hsm[];
    const int t = threadIdx.x, wid = t >> 5, lane = t & 31;
    const uint32_t sb = smem_u32(hsm);

    const int lrow = t >> 1;
    const int segH = (t & 1) * 16;
    const __nv_bfloat16* gsrc[6];
    uint32_t sdst[6];
    gsrc[0] = g_xh + (size_t)(m0 + lrow) * GK + segH;
    sdst[0] = (uint32_t)(lrow * 80) + segH * 2;
    gsrc[1] = g_xh + (size_t)(m0 + 128 + lrow) * GK + segH;
    sdst[1] = (uint32_t)((128 + lrow) * 80) + segH * 2;
    gsrc[2] = g_xl + (size_t)(m0 + lrow) * GK + segH;
    sdst[2] = 20480u + (uint32_t)(lrow * 80) + segH * 2;
    gsrc[3] = g_xl + (size_t)(m0 + 128 + lrow) * GK + segH;
    sdst[3] = 20480u + (uint32_t)((128 + lrow) * 80) + segH * 2;
    gsrc[4] = g_wth + woff + (size_t)(n0 + lrow) * GK + segH;
    sdst[4] = 40960u + (uint32_t)(lrow * 80) + segH * 2;
    gsrc[5] = g_wtl + woff + (size_t)(n0 + lrow) * GK + segH;
    sdst[5] = 51200u + (uint32_t)(lrow * 80) + segH * 2;

    const int warp_m = wid & 3, warp_n = wid >> 2;
    const int l16 = lane & 15, lh8 = (lane >> 4) * 8;

    float acc[4][8][4];
#pragma unroll
    for (int i = 0; i < 4; i++)
#pragma unroll
        for (int j = 0; j < 8; j++)
#pragma unroll
            for (int e = 0; e < 4; e++) acc[i][j][e] = 0.f;

#define GISSUE(c) do {                                                       \
    const uint32_t bo_ = sb + ((c) & 1) * GBUFB;                             \
    const int ko_ = (c) * 32;                                                \
    _Pragma("unroll")                                                        \
    for (int r_ = 0; r_ < 6; r_++) {                                         \
        CP16(bo_ + sdst[r_],      gsrc[r_] + ko_);                           \
        CP16(bo_ + sdst[r_] + 16, gsrc[r_] + ko_ + 8);                       \
    }                                                                        \
    CP_COMMIT();                                                             \
} while (0)

    GISSUE(0);
    for (int c = 0; c < 32; c++) {
        if (c + 1 < 32) { GISSUE(c + 1); CP_WAIT1(); }
        else            { CP_WAIT0(); }
        __syncthreads();

        const uint32_t ab = sb + (c & 1) * GBUFB;
#pragma unroll
        for (int ks = 0; ks < 32; ks += 16) {
            uint32_t ah[4][4], al[4][4];
#pragma unroll
            for (int mf = 0; mf < 4; mf++) {
                uint32_t ad = ab +
                    (uint32_t)((warp_m * 64 + mf * 16 + l16) * AST + ks + lh8) * 2;
                LDSM4(ah[mf], ad);
                LDSM4(al[mf], ad + 20480);
            }
#pragma unroll
            for (int nf = 0; nf < 4; nf++) {
                uint32_t bh[4], bl[4];
                uint32_t bd = ab + 40960u +
                    (uint32_t)((warp_n * 64 + nf * 16 + l16) * AST + ks + lh8) * 2;
                LDSM4(bh, bd);
                LDSM4(bl, bd + 10240);
#pragma unroll
                for (int mf = 0; mf < 4; mf++)
#pragma unroll
                    for (int j = 0; j < 2; j++) {
                        float* d = acc[mf][nf * 2 + j];
                        MMA16816(d, ah[mf], bh[j], bh[j + 2]);
                        MMA16816(d, ah[mf], bl[j], bl[j + 2]);
                        MMA16816(d, al[mf], bh[j], bh[j + 2]);
                    }
            }
        }
        __syncthreads();
    }

    const int er = lane >> 2, ec = (lane & 3) * 2;
#pragma unroll
    for (int mf = 0; mf < 4; mf++)
#pragma unroll
        for (int n8 = 0; n8 < 8; n8++) {
            int m = m0 + warp_m * 64 + mf * 16 + er;
            int n = n0 + warp_n * 64 + n8 * 8 + ec;
            float bx = bias[n], by = bias[n + 1];
            float* a4 = acc[mf][n8];
            if (Cf) {
                *(float2*)&Cf[(size_t)m * GN + n] =
                    make_float2(a4[0] + bx, a4[1] + by);
                *(float2*)&Cf[(size_t)(m + 8) * GN + n] =
                    make_float2(a4[2] + bx, a4[3] + by);
            } else {
                uint32_t hp, lp;
                sp2(a4[0] + bx, a4[1] + by, hp, lp);
                *(uint32_t*)&Ch[(size_t)m * GN + n] = hp;
                *(uint32_t*)&Cl[(size_t)m * GN + n] = lp;
                sp2(a4[2] + bx, a4[3] + by, hp, lp);
                *(uint32_t*)&Ch[(size_t)(m + 8) * GN + n] = hp;
                *(uint32_t*)&Cl[(size_t)(m + 8) * GN + n] = lp;
            }
        }
#undef GISSUE
}

__global__ __launch_bounds__(256, 1)
void hgemm_qkv(const float* __restrict__ bq, const float* __restrict__ bk,
               const float* __restrict__ bv)
{
    const int which = blockIdx.x >> 3;
    const int n0 = (blockIdx.x & 7) * 128;
    const int m0 = blockIdx.y * 256;
    __nv_bfloat16 *Ch, *Cl;
    const float* bias;
    if (which == 0)      { Ch = g_qh; Cl = g_ql; bias = bq; }
    else if (which == 1) { Ch = g_kh; Cl = g_kl; bias = bk; }
    else                 { Ch = g_vh; Cl = g_vl; bias = bv; }
    hgemm_body(which * HID * HID, bias, nullptr, Ch, Cl, m0, n0);
}

__global__ __launch_bounds__(256, 1)
void hgemm_o(const float* __restrict__ bo, float* __restrict__ out)
{
    hgemm_body(3 * HID * HID, bo, out, nullptr, nullptr,
               blockIdx.y * 256, blockIdx.x * 128);
}

// ============================================================================
// Fused HMMA sliding-window attention (FA2-style register P reuse).
// One chunk loop: stage K+V (cp.async, pre-split), QK MMAs -> exp in regs ->
// A-fragments for PV MMAs with V B-frags via ldmatrix.trans. P smem kept only
// for the probs output. Cross-warp ctx reduction at the end.
// smem (bytes):
//   Ph 0 (35328) | Pl 35328 (35328)
//   Kh 70656 (9216) | Kl 79872 (9216) | Vh 89088 (9216) | Vl 98304 (9216)
//   Q hi/lo overlays Kh/Kl area before the loop; red (8x16x64 f32 = 32768)
//   overlays K/V after the loop. part @107520 (1024) | sinv @108544 (128)
// ============================================================================
#define KSTH  72
#define PSTH  552
#define APHB  0
#define APLB  35328
#define AKHB  70656
#define AKLB  79872
#define AVHB  89088
#define AVLB  98304
#define AQHB  70656
#define AQLB  75264
#define ARED  70656
#define APRT  107520
#define ASNV  108544
#define ASMEM 108672

__global__ __launch_bounds__(256, 2)
void attn_kernel(float* __restrict__ probs, int write_probs)
{
    extern __shared__ __align__(128) char am[];
    const uint32_t sb = smem_u32(am);

    const int t    = threadIdx.x;
    const int lane = t & 31;
    const int w    = t >> 5;
    const int q0   = blockIdx.x * QT;
    const int h    = blockIdx.y;
    const int hoff = h * HD;
    const int kmin = q0 - HALF;

    float* part = (float*)(am + APRT);
    float* sinv = (float*)(am + ASNV);
    part[t] = 0.f;

    // ---- stage Q (pre-split) via cp.async into the K-buffer overlay ----
    if (t < 128) {
        int row = t >> 2, dg = (t & 3) * 16;
        const __nv_bfloat16* sh = g_qh + (size_t)(q0 + row) * HID + hoff + dg;
        const __nv_bfloat16* sl = g_ql + (size_t)(q0 + row) * HID + hoff + dg;
        uint32_t o = sb + (uint32_t)(row * KSTH + dg) * 2;
        CP16(o + AQHB, sh);
        CP16(o + AQHB + 16, sh + 8);
        CP16(o + AQLB, sl);
        CP16(o + AQLB + 16, sl + 8);
    }
    CP_COMMIT();
    CP_WAIT0();
    __syncthreads();

    const int mt  = w & 1;
    const int nb  = (w >> 1) * 16;
    const int l16 = lane & 15, lh8 = (lane >> 4) * 8;

    uint32_t qh[4][4], ql[4][4];
#pragma unroll
    for (int ks = 0; ks < 4; ks++) {
        uint32_t ad = sb + AQHB + (uint32_t)((mt * 16 + l16) * KSTH + ks * 16 + lh8) * 2;
        LDSM4(qh[ks], ad);
        LDSM4(ql[ks], ad + (AQLB - AQHB));
    }
    __syncthreads();   // Q frags read before K staging overwrites overlay

    float rs0 = 0.f, rs1 = 0.f;
    const int r0 = mt * 16 + (lane >> 2), r1 = r0 + 8;

    float acc2[8][4];
#pragma unroll
    for (int j = 0; j < 8; j++)
#pragma unroll
        for (int e = 0; e < 4; e++) acc2[j][e] = 0.f;

    for (int cc = 0; cc < 9; cc++) {
        const int cb = cc * 64;
        const int W  = (cc == 8) ? 32 : 64;

        // stage K + V (pre-split) via cp.async; zero-fill OOB keys
        {
            int row = t >> 2, dg = (t & 3) * 16;
            if (row < W) {
                int key = kmin + cb + row;
                bool ok = (key >= 0 && key < S_LEN);
                int keyc = ok ? key : 0;
                int sz = ok ? 16 : 0;
                size_t go = (size_t)keyc * HID + hoff + dg;
                uint32_t o = sb + (uint32_t)(row * KSTH + dg) * 2;
                CP16Z(o + AKHB, g_kh + go, sz);
                CP16Z(o + AKHB + 16, g_kh + go + 8, sz);
                CP16Z(o + AKLB, g_kl + go, sz);
                CP16Z(o + AKLB + 16, g_kl + go + 8, sz);
                CP16Z(o + AVHB, g_vh + go, sz);
                CP16Z(o + AVHB + 16, g_vh + go + 8, sz);
                CP16Z(o + AVLB, g_vl + go, sz);
                CP16Z(o + AVLB + 16, g_vl + go + 8, sz);
            }
        }
        CP_COMMIT();
        CP_WAIT0();
        __syncthreads();

        if (nb < W) {
            // ---- QK: 16q x 16key tile ----
            float acc[2][4];
#pragma unroll
            for (int j = 0; j < 2; j++)
#pragma unroll
                for (int e = 0; e < 4; e++) acc[j][e] = 0.f;

#pragma unroll
            for (int ks = 0; ks < 4; ks++) {
                uint32_t bh[4], bl[4];
                uint32_t bd = sb + AKHB +
                    (uint32_t)((nb + l16) * KSTH + ks * 16 + lh8) * 2;
                LDSM4(bh, bd);
                LDSM4(bl, bd + (AKLB - AKHB));
#pragma unroll
                for (int j = 0; j < 2; j++) {
                    MMA16816(acc[j], qh[ks], bh[j], bh[j + 2]);
                    MMA16816(acc[j], qh[ks], bl[j], bl[j + 2]);
                    MMA16816(acc[j], ql[ks], bh[j], bh[j + 2]);
                }
            }

            // ---- exp + mask -> P fragments (registers) + P smem (probs) ----
            uint32_t aPh[4], aPl[4];
#pragma unroll
            for (int j = 0; j < 2; j++) {
                int c0 = cb + nb + j * 8 + (lane & 3) * 2;
                float o00 = ((unsigned)(c0 - r0) < WIN)
                            ? __expf(acc[j][0] * 0.125f) : 0.f;
                float o01 = ((unsigned)(c0 + 1 - r0) < WIN)
                            ? __expf(acc[j][1] * 0.125f) : 0.f;
                float o10 = ((unsigned)(c0 - r1) < WIN)
                            ? __expf(acc[j][2] * 0.125f) : 0.f;
                float o11 = ((unsigned)(c0 + 1 - r1) < WIN)
                            ? __expf(acc[j][3] * 0.125f) : 0.f;
                rs0 += o00 + o01;
                rs1 += o10 + o11;
                uint32_t hp0, lp0, hp1, lp1;
                sp2(o00, o01, hp0, lp0);
                sp2(o10, o11, hp1, lp1);
                aPh[j * 2]     = hp0;
                aPl[j * 2]     = lp0;
                aPh[j * 2 + 1] = hp1;
                aPl[j * 2 + 1] = lp1;
                *(uint32_t*)(am + APHB + (uint32_t)(r0 * PSTH + c0) * 2) = hp0;
                *(uint32_t*)(am + APLB + (uint32_t)(r0 * PSTH + c0) * 2) = lp0;
                *(uint32_t*)(am + APHB + (uint32_t)(r1 * PSTH + c0) * 2) = hp1;
                *(uint32_t*)(am + APLB + (uint32_t)(r1 * PSTH + c0) * 2) = lp1;
            }

            // ---- PV: P(16q x 16key) @ V(16key x 64d), V B-frags via trans ----
#pragma unroll
            for (int nf = 0; nf < 4; nf++) {
                uint32_t vh4[4], vl4[4];
                uint32_t vd = sb + AVHB +
                    (uint32_t)((nb + l16) * KSTH + nf * 16 + lh8) * 2;
                LDSM4T(vh4, vd);
                LDSM4T(vl4, vd + (AVLB - AVHB));
#pragma unroll
                for (int j2 = 0; j2 < 2; j2++) {
                    float* d = acc2[nf * 2 + j2];
                    MMA16816(d, aPh, vh4[j2 * 2], vh4[j2 * 2 + 1]);
                    MMA16816(d, aPh, vl4[j2 * 2], vl4[j2 * 2 + 1]);
                    MMA16816(d, aPl, vh4[j2 * 2], vh4[j2 * 2 + 1]);
                }
            }
        }
        __syncthreads();   // compute done before next chunk staging
    }

    // ---- deterministic row sums ----
    rs0 += __shfl_xor_sync(0xFFFFFFFFu, rs0, 1);
    rs0 += __shfl_xor_sync(0xFFFFFFFFu, rs0, 2);
    rs1 += __shfl_xor_sync(0xFFFFFFFFu, rs1, 1);
    rs1 += __shfl_xor_sync(0xFFFFFFFFu, rs1, 2);
    if ((lane & 3) == 0) {
        part[w * 32 + r0] = rs0;
        part[w * 32 + r1] = rs1;
    }
    __syncthreads();
    if (t < 32) {
        float s = 0.f;
#pragma unroll
        for (int w8 = 0; w8 < 8; w8++) s += part[w8 * 32 + t];
        sinv[t] = 1.f / s;
    }
    __syncthreads();

    // ---- probs write ----
    if (write_probs) {
        float* pr = probs + ((size_t)h * S_LEN + q0) * WIN;
        for (int idx = t; idx < QT * WIN; idx += 256) {
            int qi = idx >> 9, ww = idx & (WIN - 1);
            uint32_t o = (uint32_t)(qi * PSTH + qi + ww) * 2;
            float ph = __bfloat162float(*(__nv_bfloat16*)(am + APHB + o));
            float pl = __bfloat162float(*(__nv_bfloat16*)(am + APLB + o));
            pr[(size_t)qi * WIN + ww] = (ph + pl) * sinv[qi];
        }
    }

    // ---- cross-warp ctx reduction (red overlays K/V area) ----
    {
        char* red = am + ARED + w * 4096;
        const int g = lane >> 2, dc = (lane & 3) * 2;
#pragma unroll
        for (int n8 = 0; n8 < 8; n8++) {
            int d = n8 * 8 + dc;
            *(float2*)(red + g * 256 + d * 4) =
                make_float2(acc2[n8][0], acc2[n8][1]);
            *(float2*)(red + (g + 8) * 256 + d * 4) =
                make_float2(acc2[n8][2], acc2[n8][3]);
        }
    }
    __syncthreads();

    // ---- sum 4 key-slice partials per q-tile, scale, split-write ----
    {
        int q = t >> 3, d0 = (t & 7) * 8;
        int mtq = q >> 4, qr = q & 15;
        float v[8];
#pragma unroll
        for (int e = 0; e < 8; e++) v[e] = 0.f;
#pragma unroll
        for (int wb = 0; wb < 4; wb++) {
            const float* rb =
                (const float*)(am + ARED + (mtq + wb * 2) * 4096 + qr * 256 + d0 * 4);
#pragma unroll
            for (int e = 0; e < 8; e++) v[e] += rb[e];
        }
        float iv = sinv[q];
        size_t o = (size_t)(q0 + q) * HID + hoff + d0;
#pragma unroll
        for (int p = 0; p < 4; p++) {
            uint32_t hp, lp;
            sp2(v[p * 2] * iv, v[p * 2 + 1] * iv, hp, lp);
            *(uint32_t*)&g_xh[o + p * 2] = hp;
            *(uint32_t*)&g_xl[o + p * 2] = lp;
        }
    }
}

// ============================================================================
extern "C" void kernel_launch(void* const* d_in, const int* in_sizes, int n_in,
                              void* d_out, int out_size)
{
    const float* X  = (const float*)d_in[0];
    const float* Wq = (const float*)d_in[1];
    const float* bq = (const float*)d_in[2];
    const float* Wk = (const float*)d_in[3];
    const float* bk = (const float*)d_in[4];
    const float* Wv = (const float*)d_in[5];
    const float* bv = (const float*)d_in[6];
    const float* Wo = (const float*)d_in[7];
    const float* bo = (const float*)d_in[8];

    float* out = (float*)d_out;
    const size_t OUT_ELEMS   = (size_t)S_LEN * HID;
    const size_t PROBS_ELEMS = (size_t)NH * S_LEN * WIN;
    float* probs = out + OUT_ELEMS;
    int write_probs = ((size_t)out_size >= OUT_ELEMS + PROBS_ELEMS) ? 1 : 0;

    cudaFuncSetAttribute(attn_kernel,
                         cudaFuncAttributeMaxDynamicSharedMemorySize, ASMEM);
    cudaFuncSetAttribute(hgemm_qkv,
                         cudaFuncAttributeMaxDynamicSharedMemorySize, GSMEM);
    cudaFuncSetAttribute(hgemm_o,
                         cudaFuncAttributeMaxDynamicSharedMemorySize, GSMEM);

    conv_act<<<(S_LEN * HID) / 1024, 256>>>(X);
    dim3 ct(32, 8), cg(HID / 32, HID / 32);
    conv_w_t<<<cg, ct>>>(Wq, 0);
    conv_w_t<<<cg, ct>>>(Wk, HID * HID);
    conv_w_t<<<cg, ct>>>(Wv, 2 * HID * HID);
    conv_w_t<<<cg, ct>>>(Wo, 3 * HID * HID);

    hgemm_qkv<<<dim3(24, 16), 256, GSMEM>>>(bq, bk, bv);

    dim3 agrid(S_LEN / QT, NH);
    attn_kernel<<<agrid, 256, ASMEM>>>(probs, write_probs);

    hgemm_o<<<dim3(8, 16), 256, GSMEM>>>(bo, out);
}

// round 17
// speedup vs baseline: 1.2402x; 1.2401x over previous
#include <cuda_runtime.h>
#include <cuda_bf16.h>
#include <cuda_fp16.h>
#include <cstdint>

#define S_LEN 4096
#define HID   1024
#define NH    16
#define HD    64
#define WIN   512
#define HALF  256
#define QT    32
#define GK    1024
#define GN    1024

// ---- scratch (no cudaMalloc allowed); referenced only from device code ----
__device__ __half g_xh[S_LEN * HID];           // X / ctx split-fp16 (GEMM A)
__device__ __half g_xl[S_LEN * HID];
__device__ __half g_wth[4 * HID * HID];        // weights, single fp16, [N,K]
__device__ __nv_bfloat16 g_qh[S_LEN * HID];    // attention operands, bf16 split
__device__ __nv_bfloat16 g_ql[S_LEN * HID];
__device__ __nv_bfloat16 g_kh[S_LEN * HID];
__device__ __nv_bfloat16 g_kl[S_LEN * HID];
__device__ __nv_bfloat16 g_vh[S_LEN * HID];
__device__ __nv_bfloat16 g_vl[S_LEN * HID];

__device__ __forceinline__ uint32_t smem_u32(const void* p) {
    uint32_t a;
    asm("{ .reg .u64 t; cvta.to.shared.u64 t, %1; cvt.u32.u64 %0, t; }"
        : "=r"(a) : "l"(p));
    return a;
}

#define CP16(dst, src) \
    asm volatile("cp.async.cg.shared.global [%0], [%1], 16;" \
                 :: "r"(dst), "l"(src) : "memory")
#define CP16Z(dst, src, sz) \
    asm volatile("cp.async.cg.shared.global [%0], [%1], 16, %2;" \
                 :: "r"(dst), "l"(src), "r"(sz) : "memory")
#define CP_COMMIT() asm volatile("cp.async.commit_group;" ::: "memory")
#define CP_WAIT1()  asm volatile("cp.async.wait_group 1;" ::: "memory")
#define CP_WAIT0()  asm volatile("cp.async.wait_group 0;" ::: "memory")

#define LDSM4(r, a) \
    asm volatile("ldmatrix.sync.aligned.m8n8.x4.shared.b16 {%0,%1,%2,%3}, [%4];" \
                 : "=r"((r)[0]), "=r"((r)[1]), "=r"((r)[2]), "=r"((r)[3]) \
                 : "r"(a))
#define LDSM4T(r, a) \
    asm volatile("ldmatrix.sync.aligned.m8n8.x4.trans.shared.b16 {%0,%1,%2,%3}, [%4];" \
                 : "=r"((r)[0]), "=r"((r)[1]), "=r"((r)[2]), "=r"((r)[3]) \
                 : "r"(a))

// bf16 MMA (attention)
#define MMA16816(d, a, b0, b1) \
    asm volatile("mma.sync.aligned.m16n8k16.row.col.f32.bf16.bf16.f32 " \
                 "{%0,%1,%2,%3}, {%4,%5,%6,%7}, {%8,%9}, {%0,%1,%2,%3};" \
                 : "+f"((d)[0]), "+f"((d)[1]), "+f"((d)[2]), "+f"((d)[3]) \
                 : "r"((a)[0]), "r"((a)[1]), "r"((a)[2]), "r"((a)[3]), \
                   "r"(b0), "r"(b1))
// fp16 MMA (projection GEMMs)
#define MMA16816H(d, a, b0, b1) \
    asm volatile("mma.sync.aligned.m16n8k16.row.col.f32.f16.f16.f32 " \
                 "{%0,%1,%2,%3}, {%4,%5,%6,%7}, {%8,%9}, {%0,%1,%2,%3};" \
                 : "+f"((d)[0]), "+f"((d)[1]), "+f"((d)[2]), "+f"((d)[3]) \
                 : "r"((a)[0]), "r"((a)[1]), "r"((a)[2]), "r"((a)[3]), \
                   "r"(b0), "r"(b1))

__device__ __forceinline__ void split_bf16(float v, __nv_bfloat16& h,
                                           __nv_bfloat16& l) {
    h = __float2bfloat16(v);
    l = __float2bfloat16(v - __bfloat162float(h));
}
__device__ __forceinline__ uint32_t pk2(__nv_bfloat16 a, __nv_bfloat16 b) {
    return ((uint32_t)__bfloat16_as_ushort(b) << 16) | __bfloat16_as_ushort(a);
}
__device__ __forceinline__ void sp2(float a, float b, uint32_t& hp, uint32_t& lp) {
    __nv_bfloat16 ha, la, hb, lb;
    split_bf16(a, ha, la);
    split_bf16(b, hb, lb);
    hp = pk2(ha, hb);
    lp = pk2(la, lb);
}
// fp16 split pack
__device__ __forceinline__ void sp2h(float a, float b, uint32_t& hp, uint32_t& lp) {
    __half ha = __float2half_rn(a);
    __half la = __float2half_rn(a - __half2float(ha));
    __half hb = __float2half_rn(b);
    __half lb = __float2half_rn(b - __half2float(hb));
    hp = ((uint32_t)__half_as_ushort(hb) << 16) | __half_as_ushort(ha);
    lp = ((uint32_t)__half_as_ushort(lb) << 16) | __half_as_ushort(la);
}

// ============================================================================
// convert X -> g_xh/g_xl (fp16 split)
// ============================================================================
__global__ __launch_bounds__(256)
void conv_act(const float* __restrict__ src)
{
    size_t i = (size_t)blockIdx.x * 256 + threadIdx.x;
    float4 v = *(const float4*)(src + i * 4);
    uint2 hp, lp;
    sp2h(v.x, v.y, hp.x, lp.x);
    sp2h(v.z, v.w, hp.y, lp.y);
    *(uint2*)&g_xh[i * 4] = hp;
    *(uint2*)&g_xl[i * 4] = lp;
}

// ============================================================================
// all 4 weights: W[K,N] -> g_wth[N,K] fp16 single; blockIdx.z selects weight
// ============================================================================
__global__ __launch_bounds__(256)
void conv_w_t(const float* __restrict__ W0, const float* __restrict__ W1,
              const float* __restrict__ W2, const float* __restrict__ W3)
{
    __shared__ float tile[32][33];
    const int tx = threadIdx.x, ty = threadIdx.y;
    const int z = blockIdx.z;
    const float* W = (z == 0) ? W0 : (z == 1) ? W1 : (z == 2) ? W2 : W3;
    const int woff = z * HID * HID;
#pragma unroll
    for (int j = 0; j < 4; j++)
        tile[ty + 8 * j][tx] =
            W[(size_t)(blockIdx.y * 32 + ty + 8 * j) * HID + blockIdx.x * 32 + tx];
    __syncthreads();
#pragma unroll
    for (int j = 0; j < 4; j++) {
        float v = tile[tx][ty + 8 * j];
        size_t o = (size_t)woff +
                   (size_t)(blockIdx.x * 32 + ty + 8 * j) * HID + blockIdx.y * 32 + tx;
        g_wth[o] = __float2half_rn(v);
    }
}

// ============================================================================
// 2-MMA fp16-split HMMA GEMM: C = (Ah+Al) @ Wh + bias
// Block tile 256m x 128n, BK=32, warps 4m x 2n (warp tile 64x64).
// smem/buffer: Ah 256x80 @0 | Al @20480 | B 128x80 @40960 -> 51200 B, x2 buf.
// ============================================================================
#define AST   40
#define GBUFB 51200
#define GSMEM (2 * GBUFB)

__device__ __forceinline__ void hgemm_body(
    int woff, const float* __restrict__ bias,
    float* __restrict__ Cf,
    __nv_bfloat16* __restrict__ Ch, __nv_bfloat16* __restrict__ Cl,
    int m0, int n0)
{
    extern __shared__ __align__(128) char hsm[];
    const int t = threadIdx.x, wid = t >> 5, lane = t & 31;
    const uint32_t sb = smem_u32(hsm);

    const int lrow = t >> 1;
    const int segH = (t & 1) * 16;
    const __half* gsrc[5];
    uint32_t sdst[5];
    gsrc[0] = g_xh + (size_t)(m0 + lrow) * GK + segH;
    sdst[0] = (uint32_t)(lrow * 80) + segH * 2;
    gsrc[1] = g_xh + (size_t)(m0 + 128 + lrow) * GK + segH;
    sdst[1] = (uint32_t)((128 + lrow) * 80) + segH * 2;
    gsrc[2] = g_xl + (size_t)(m0 + lrow) * GK + segH;
    sdst[2] = 20480u + (uint32_t)(lrow * 80) + segH * 2;
    gsrc[3] = g_xl + (size_t)(m0 + 128 + lrow) * GK + segH;
    sdst[3] = 20480u + (uint32_t)((128 + lrow) * 80) + segH * 2;
    gsrc[4] = g_wth + woff + (size_t)(n0 + lrow) * GK + segH;
    sdst[4] = 40960u + (uint32_t)(lrow * 80) + segH * 2;

    const int warp_m = wid & 3, warp_n = wid >> 2;
    const int l16 = lane & 15, lh8 = (lane >> 4) * 8;

    float acc[4][8][4];
#pragma unroll
    for (int i = 0; i < 4; i++)
#pragma unroll
        for (int j = 0; j < 8; j++)
#pragma unroll
            for (int e = 0; e < 4; e++) acc[i][j][e] = 0.f;

#define GISSUE(c) do {                                                       \
    const uint32_t bo_ = sb + ((c) & 1) * GBUFB;                             \
    const int ko_ = (c) * 32;                                                \
    _Pragma("unroll")                                                        \
    for (int r_ = 0; r_ < 5; r_++) {                                         \
        CP16(bo_ + sdst[r_],      gsrc[r_] + ko_);                           \
        CP16(bo_ + sdst[r_] + 16, gsrc[r_] + ko_ + 8);                       \
    }                                                                        \
    CP_COMMIT();                                                             \
} while (0)

    GISSUE(0);
    for (int c = 0; c < 32; c++) {
        if (c + 1 < 32) { GISSUE(c + 1); CP_WAIT1(); }
        else            { CP_WAIT0(); }
        __syncthreads();

        const uint32_t ab = sb + (c & 1) * GBUFB;
#pragma unroll
        for (int ks = 0; ks < 32; ks += 16) {
            uint32_t ah[4][4], al[4][4];
#pragma unroll
            for (int mf = 0; mf < 4; mf++) {
                uint32_t ad = ab +
                    (uint32_t)((warp_m * 64 + mf * 16 + l16) * AST + ks + lh8) * 2;
                LDSM4(ah[mf], ad);
                LDSM4(al[mf], ad + 20480);
            }
#pragma unroll
            for (int nf = 0; nf < 4; nf++) {
                uint32_t bh[4];
                uint32_t bd = ab + 40960u +
                    (uint32_t)((warp_n * 64 + nf * 16 + l16) * AST + ks + lh8) * 2;
                LDSM4(bh, bd);
#pragma unroll
                for (int mf = 0; mf < 4; mf++)
#pragma unroll
                    for (int j = 0; j < 2; j++) {
                        float* d = acc[mf][nf * 2 + j];
                        MMA16816H(d, ah[mf], bh[j], bh[j + 2]);
                        MMA16816H(d, al[mf], bh[j], bh[j + 2]);
                    }
            }
        }
        __syncthreads();
    }

    const int er = lane >> 2, ec = (lane & 3) * 2;
#pragma unroll
    for (int mf = 0; mf < 4; mf++)
#pragma unroll
        for (int n8 = 0; n8 < 8; n8++) {
            int m = m0 + warp_m * 64 + mf * 16 + er;
            int n = n0 + warp_n * 64 + n8 * 8 + ec;
            float bx = bias[n], by = bias[n + 1];
            float* a4 = acc[mf][n8];
            if (Cf) {
                *(float2*)&Cf[(size_t)m * GN + n] =
                    make_float2(a4[0] + bx, a4[1] + by);
                *(float2*)&Cf[(size_t)(m + 8) * GN + n] =
                    make_float2(a4[2] + bx, a4[3] + by);
            } else {
                uint32_t hp, lp;
                sp2(a4[0] + bx, a4[1] + by, hp, lp);
                *(uint32_t*)&Ch[(size_t)m * GN + n] = hp;
                *(uint32_t*)&Cl[(size_t)m * GN + n] = lp;
                sp2(a4[2] + bx, a4[3] + by, hp, lp);
                *(uint32_t*)&Ch[(size_t)(m + 8) * GN + n] = hp;
                *(uint32_t*)&Cl[(size_t)(m + 8) * GN + n] = lp;
            }
        }
#undef GISSUE
}

__global__ __launch_bounds__(256, 1)
void hgemm_qkv(const float* __restrict__ bq, const float* __restrict__ bk,
               const float* __restrict__ bv)
{
    const int which = blockIdx.x >> 3;
    const int n0 = (blockIdx.x & 7) * 128;
    const int m0 = blockIdx.y * 256;
    __nv_bfloat16 *Ch, *Cl;
    const float* bias;
    if (which == 0)      { Ch = g_qh; Cl = g_ql; bias = bq; }
    else if (which == 1) { Ch = g_kh; Cl = g_kl; bias = bk; }
    else                 { Ch = g_vh; Cl = g_vl; bias = bv; }
    hgemm_body(which * HID * HID, bias, nullptr, Ch, Cl, m0, n0);
}

__global__ __launch_bounds__(256, 1)
void hgemm_o(const float* __restrict__ bo, float* __restrict__ out)
{
    hgemm_body(3 * HID * HID, bo, out, nullptr, nullptr,
               blockIdx.y * 256, blockIdx.x * 128);
}

// ============================================================================
// Fused HMMA sliding-window attention (bf16 3-MMA split, unchanged math).
// K and V staged in separate cp.async groups: V latency hidden behind QK.
// ctx epilogue writes fp16 split into g_xh/g_xl (A of hgemm_o).
// ============================================================================
#define KSTH  72
#define PSTH  552
#define APHB  0
#define APLB  35328
#define AKHB  70656
#define AKLB  79872
#define AVHB  89088
#define AVLB  98304
#define AQHB  70656
#define AQLB  75264
#define ARED  70656
#define APRT  107520
#define ASNV  108544
#define ASMEM 108672

__global__ __launch_bounds__(256, 2)
void attn_kernel(float* __restrict__ probs, int write_probs)
{
    extern __shared__ __align__(128) char am[];
    const uint32_t sb = smem_u32(am);

    const int t    = threadIdx.x;
    const int lane = t & 31;
    const int w    = t >> 5;
    const int q0   = blockIdx.x * QT;
    const int h    = blockIdx.y;
    const int hoff = h * HD;
    const int kmin = q0 - HALF;

    float* part = (float*)(am + APRT);
    float* sinv = (float*)(am + ASNV);
    part[t] = 0.f;

    // ---- stage Q (pre-split) via cp.async into the K-buffer overlay ----
    if (t < 128) {
        int row = t >> 2, dg = (t & 3) * 16;
        const __nv_bfloat16* sh = g_qh + (size_t)(q0 + row) * HID + hoff + dg;
        const __nv_bfloat16* sl = g_ql + (size_t)(q0 + row) * HID + hoff + dg;
        uint32_t o = sb + (uint32_t)(row * KSTH + dg) * 2;
        CP16(o + AQHB, sh);
        CP16(o + AQHB + 16, sh + 8);
        CP16(o + AQLB, sl);
        CP16(o + AQLB + 16, sl + 8);
    }
    CP_COMMIT();
    CP_WAIT0();
    __syncthreads();

    const int mt  = w & 1;
    const int nb  = (w >> 1) * 16;
    const int l16 = lane & 15, lh8 = (lane >> 4) * 8;

    uint32_t qh[4][4], ql[4][4];
#pragma unroll
    for (int ks = 0; ks < 4; ks++) {
        uint32_t ad = sb + AQHB + (uint32_t)((mt * 16 + l16) * KSTH + ks * 16 + lh8) * 2;
        LDSM4(qh[ks], ad);
        LDSM4(ql[ks], ad + (AQLB - AQHB));
    }
    __syncthreads();   // Q frags read before K staging overwrites overlay

    float rs0 = 0.f, rs1 = 0.f;
    const int r0 = mt * 16 + (lane >> 2), r1 = r0 + 8;

    float acc2[8][4];
#pragma unroll
    for (int j = 0; j < 8; j++)
#pragma unroll
        for (int e = 0; e < 4; e++) acc2[j][e] = 0.f;

    for (int cc = 0; cc < 9; cc++) {
        const int cb = cc * 64;
        const int W  = (cc == 8) ? 32 : 64;

        // stage K (group 1) then V (group 0); zero-fill OOB keys
        {
            int row = t >> 2, dg = (t & 3) * 16;
            int key = kmin + cb + row;
            bool ok = (key >= 0 && key < S_LEN);
            int keyc = ok ? key : 0;
            int sz = (ok && row < W) ? 16 : 0;
            size_t go = (size_t)keyc * HID + hoff + dg;
            uint32_t o = sb + (uint32_t)(row * KSTH + dg) * 2;
            if (row < W) {
                CP16Z(o + AKHB, g_kh + go, sz);
                CP16Z(o + AKHB + 16, g_kh + go + 8, sz);
                CP16Z(o + AKLB, g_kl + go, sz);
                CP16Z(o + AKLB + 16, g_kl + go + 8, sz);
            }
            CP_COMMIT();
            if (row < W) {
                CP16Z(o + AVHB, g_vh + go, sz);
                CP16Z(o + AVHB + 16, g_vh + go + 8, sz);
                CP16Z(o + AVLB, g_vl + go, sz);
                CP16Z(o + AVLB + 16, g_vl + go + 8, sz);
            }
            CP_COMMIT();
        }
        CP_WAIT1();            // K complete; V may still be in flight
        __syncthreads();

        uint32_t aPh[4], aPl[4];
        bool active = (nb < W);
        if (active) {
            // ---- QK: 16q x 16key tile ----
            float acc[2][4];
#pragma unroll
            for (int j = 0; j < 2; j++)
#pragma unroll
                for (int e = 0; e < 4; e++) acc[j][e] = 0.f;

#pragma unroll
            for (int ks = 0; ks < 4; ks++) {
                uint32_t bh[4], bl[4];
                uint32_t bd = sb + AKHB +
                    (uint32_t)((nb + l16) * KSTH + ks * 16 + lh8) * 2;
                LDSM4(bh, bd);
                LDSM4(bl, bd + (AKLB - AKHB));
#pragma unroll
                for (int j = 0; j < 2; j++) {
                    MMA16816(acc[j], qh[ks], bh[j], bh[j + 2]);
                    MMA16816(acc[j], qh[ks], bl[j], bl[j + 2]);
                    MMA16816(acc[j], ql[ks], bh[j], bh[j + 2]);
                }
            }

            // ---- exp + mask -> P fragments + P smem (for probs) ----
#pragma unroll
            for (int j = 0; j < 2; j++) {
                int c0 = cb + nb + j * 8 + (lane & 3) * 2;
                float o00 = ((unsigned)(c0 - r0) < WIN)
                            ? __expf(acc[j][0] * 0.125f) : 0.f;
                float o01 = ((unsigned)(c0 + 1 - r0) < WIN)
                            ? __expf(acc[j][1] * 0.125f) : 0.f;
                float o10 = ((unsigned)(c0 - r1) < WIN)
                            ? __expf(acc[j][2] * 0.125f) : 0.f;
                float o11 = ((unsigned)(c0 + 1 - r1) < WIN)
                            ? __expf(acc[j][3] * 0.125f) : 0.f;
                rs0 += o00 + o01;
                rs1 += o10 + o11;
                uint32_t hp0, lp0, hp1, lp1;
                sp2(o00, o01, hp0, lp0);
                sp2(o10, o11, hp1, lp1);
                aPh[j * 2]     = hp0;
                aPl[j * 2]     = lp0;
                aPh[j * 2 + 1] = hp1;
                aPl[j * 2 + 1] = lp1;
                *(uint32_t*)(am + APHB + (uint32_t)(r0 * PSTH + c0) * 2) = hp0;
                *(uint32_t*)(am + APLB + (uint32_t)(r0 * PSTH + c0) * 2) = lp0;
                *(uint32_t*)(am + APHB + (uint32_t)(r1 * PSTH + c0) * 2) = hp1;
                *(uint32_t*)(am + APLB + (uint32_t)(r1 * PSTH + c0) * 2) = lp1;
            }
        }

        CP_WAIT0();            // V now complete
        __syncthreads();

        if (active) {
            // ---- PV: P(16q x 16key) @ V(16key x 64d) via trans B-frags ----
#pragma unroll
            for (int nf = 0; nf < 4; nf++) {
                uint32_t vh4[4], vl4[4];
                uint32_t vd = sb + AVHB +
                    (uint32_t)((nb + l16) * KSTH + nf * 16 + lh8) * 2;
                LDSM4T(vh4, vd);
                LDSM4T(vl4, vd + (AVLB - AVHB));
#pragma unroll
                for (int j2 = 0; j2 < 2; j2++) {
                    float* d = acc2[nf * 2 + j2];
                    MMA16816(d, aPh, vh4[j2 * 2], vh4[j2 * 2 + 1]);
                    MMA16816(d, aPh, vl4[j2 * 2], vl4[j2 * 2 + 1]);
                    MMA16816(d, aPl, vh4[j2 * 2], vh4[j2 * 2 + 1]);
                }
            }
        }
        __syncthreads();   // compute done before next chunk staging
    }

    // ---- deterministic row sums ----
    rs0 += __shfl_xor_sync(0xFFFFFFFFu, rs0, 1);
    rs0 += __shfl_xor_sync(0xFFFFFFFFu, rs0, 2);
    rs1 += __shfl_xor_sync(0xFFFFFFFFu, rs1, 1);
    rs1 += __shfl_xor_sync(0xFFFFFFFFu, rs1, 2);
    if ((lane & 3) == 0) {
        part[w * 32 + r0] = rs0;
        part[w * 32 + r1] = rs1;
    }
    __syncthreads();
    if (t < 32) {
        float s = 0.f;
#pragma unroll
        for (int w8 = 0; w8 < 8; w8++) s += part[w8 * 32 + t];
        sinv[t] = 1.f / s;
    }
    __syncthreads();

    // ---- probs write ----
    if (write_probs) {
        float* pr = probs + ((size_t)h * S_LEN + q0) * WIN;
        for (int idx = t; idx < QT * WIN; idx += 256) {
            int qi = idx >> 9, ww = idx & (WIN - 1);
            uint32_t o = (uint32_t)(qi * PSTH + qi + ww) * 2;
            float ph = __bfloat162float(*(__nv_bfloat16*)(am + APHB + o));
            float pl = __bfloat162float(*(__nv_bfloat16*)(am + APLB + o));
            pr[(size_t)qi * WIN + ww] = (ph + pl) * sinv[qi];
        }
    }

    // ---- cross-warp ctx reduction (red overlays K/V area) ----
    {
        char* red = am + ARED + w * 4096;
        const int g = lane >> 2, dc = (lane & 3) * 2;
#pragma unroll
        for (int n8 = 0; n8 < 8; n8++) {
            int d = n8 * 8 + dc;
            *(float2*)(red + g * 256 + d * 4) =
                make_float2(acc2[n8][0], acc2[n8][1]);
            *(float2*)(red + (g + 8) * 256 + d * 4) =
                make_float2(acc2[n8][2], acc2[n8][3]);
        }
    }
    __syncthreads();

    // ---- sum 4 key-slice partials per q-tile, scale, fp16-split write ----
    {
        int q = t >> 3, d0 = (t & 7) * 8;
        int mtq = q >> 4, qr = q & 15;
        float v[8];
#pragma unroll
        for (int e = 0; e < 8; e++) v[e] = 0.f;
#pragma unroll
        for (int wb = 0; wb < 4; wb++) {
            const float* rb =
                (const float*)(am + ARED + (mtq + wb * 2) * 4096 + qr * 256 + d0 * 4);
#pragma unroll
            for (int e = 0; e < 8; e++) v[e] += rb[e];
        }
        float iv = sinv[q];
        size_t o = (size_t)(q0 + q) * HID + hoff + d0;
#pragma unroll
        for (int p = 0; p < 4; p++) {
            uint32_t hp, lp;
            sp2h(v[p * 2] * iv, v[p * 2 + 1] * iv, hp, lp);
            *(uint32_t*)&g_xh[o + p * 2] = hp;
            *(uint32_t*)&g_xl[o + p * 2] = lp;
        }
    }
}

// ============================================================================
extern "C" void kernel_launch(void* const* d_in, const int* in_sizes, int n_in,
                              void* d_out, int out_size)
{
    const float* X  = (const float*)d_in[0];
    const float* Wq = (const float*)d_in[1];
    const float* bq = (const float*)d_in[2];
    const float* Wk = (const float*)d_in[3];
    const float* bk = (const float*)d_in[4];
    const float* Wv = (const float*)d_in[5];
    const float* bv = (const float*)d_in[6];
    const float* Wo = (const float*)d_in[7];
    const float* bo = (const float*)d_in[8];

    float* out = (float*)d_out;
    const size_t OUT_ELEMS   = (size_t)S_LEN * HID;
    const size_t PROBS_ELEMS = (size_t)NH * S_LEN * WIN;
    float* probs = out + OUT_ELEMS;
    int write_probs = ((size_t)out_size >= OUT_ELEMS + PROBS_ELEMS) ? 1 : 0;

    cudaFuncSetAttribute(attn_kernel,
                         cudaFuncAttributeMaxDynamicSharedMemorySize, ASMEM);
    cudaFuncSetAttribute(hgemm_qkv,
                         cudaFuncAttributeMaxDynamicSharedMemorySize, GSMEM);
    cudaFuncSetAttribute(hgemm_o,
                         cudaFuncAttributeMaxDynamicSharedMemorySize, GSMEM);

    conv_act<<<(S_LEN * HID) / 1024, 256>>>(X);
    dim3 ct(32, 8), cg(HID / 32, HID / 32, 4);
    conv_w_t<<<cg, ct>>>(Wq, Wk, Wv, Wo);

    hgemm_qkv<<<dim3(24, 16), 256, GSMEM>>>(bq, bk, bv);

    dim3 agrid(S_LEN / QT, NH);
    attn_kernel<<<agrid, 256, ASMEM>>>(probs, write_probs);

    hgemm_o<<<dim3(8, 16), 256, GSMEM>>>(bo, out);
}